// round 16
// baseline (speedup 1.0000x reference)
#include <cuda_runtime.h>

// GATConv forward (heads=1): N=50000, E=1600000, F_IN=128, F_OUT=64.
// edge_index is INT32. CSR-by-destination, no float atomics, no max-pass.
//
// R13 hot loops (148.3us best) with decoupled attention scalars:
//   a_src = x @ (W @ att_src) computed EARLY on stream B, so k_fill waits
//   only for {att2, scan}, never the GEMM; GEMM overlaps fill.
//   stream B: k_watt -> k_att2 -> [evAtt] -> k_gemm -> [evJoin]
//   stream A: k_build -> k_scan -> wait(evAtt) -> k_fill -> wait(evJoin) -> k_node

#define F_IN  128
#define F_OUT 64
#define MAXN  50000
#define MAXE  1600000
#define MAXM  (MAXE + MAXN)

__device__ __align__(16) float g_h[(size_t)MAXN * F_OUT];
__device__ __align__(16) float g_wa[F_IN];   // W @ att_src
__device__ __align__(16) float g_wd[F_IN];   // W @ att_dst
__device__ float  g_asrc[MAXN];
__device__ float  g_adst[MAXN];
__device__ int    g_cnt[MAXN];          // zero-init (BSS); k_fill restores to 0
__device__ int    g_rowstart[MAXN + 1];
__device__ __align__(8) float2 g_csr[MAXM];  // .x = src bits, .y = exp(e)

// ---- packed f32x2 helpers (sm_103a) ---------------------------------------
__device__ __forceinline__ unsigned long long pack2(float a, float b) {
    unsigned long long r;
    asm("mov.b64 %0, {%1, %2};" : "=l"(r) : "f"(a), "f"(b));
    return r;
}
__device__ __forceinline__ void unpack2(unsigned long long v, float& a, float& b) {
    asm("mov.b64 {%0, %1}, %2;" : "=f"(a), "=f"(b) : "l"(v));
}
__device__ __forceinline__ unsigned long long fma2(unsigned long long a,
                                                   unsigned long long b,
                                                   unsigned long long c) {
    unsigned long long d;
    asm("fma.rn.f32x2 %0, %1, %2, %3;" : "=l"(d) : "l"(a), "l"(b), "l"(c));
    return d;
}

// ---------------------------------------------------------------------------
// wa = W @ att_src, wd = W @ att_dst.  One block, 128 threads (thread = k).
__global__ void __launch_bounds__(128) k_watt(const float* __restrict__ W,
                                              const float* __restrict__ att_src,
                                              const float* __restrict__ att_dst) {
    __shared__ float as_s[F_OUT], ad_s[F_OUT];
    int t = threadIdx.x;
    if (t < F_OUT) { as_s[t] = att_src[t]; ad_s[t] = att_dst[t]; }
    __syncthreads();
    const float4* Wr = (const float4*)(W + t * F_OUT);  // row k of W
    float sa = 0.f, sd = 0.f;
#pragma unroll
    for (int f4 = 0; f4 < F_OUT / 4; f4++) {
        float4 wv = Wr[f4];
        const float* a4 = &as_s[f4 * 4];
        const float* d4 = &ad_s[f4 * 4];
        sa += wv.x * a4[0] + wv.y * a4[1] + wv.z * a4[2] + wv.w * a4[3];
        sd += wv.x * d4[0] + wv.y * d4[1] + wv.z * d4[2] + wv.w * d4[3];
    }
    g_wa[t] = sa;
    g_wd[t] = sd;
}

// ---------------------------------------------------------------------------
// a_src[i] = x[i,:]·wa, a_dst[i] = x[i,:]·wd.  One warp per node; lane l
// owns float4 l of the 128-float x row.  5-step shuffle reduction.
__global__ void __launch_bounds__(256) k_att2(const float* __restrict__ x, int n) {
    int warp = (blockIdx.x * blockDim.x + threadIdx.x) >> 5;
    int lane = threadIdx.x & 31;
    if (warp >= n) return;
    float4 xv = ((const float4*)x)[warp * 32 + lane];
    float4 wa = ((const float4*)g_wa)[lane];
    float4 wd = ((const float4*)g_wd)[lane];
    float ps = xv.x * wa.x + xv.y * wa.y + xv.z * wa.z + xv.w * wa.w;
    float pd = xv.x * wd.x + xv.y * wd.y + xv.z * wd.z + xv.w * wd.w;
#pragma unroll
    for (int o = 16; o > 0; o >>= 1) {
        ps += __shfl_xor_sync(0xFFFFFFFFu, ps, o);
        pd += __shfl_xor_sync(0xFFFFFFFFu, pd, o);
    }
    if (lane == 0) {
        g_asrc[warp] = ps;
        g_adst[warp] = pd;
    }
}

// ---------------------------------------------------------------------------
// Pure histogram: atomicAdd return unused -> compiles to REDG (no round trip).
__global__ void k_build(const int* __restrict__ dst4, int e4) {
    int i = blockIdx.x * blockDim.x + threadIdx.x;
    if (i >= e4) return;
    int4 d = ((const int4*)dst4)[i];
    atomicAdd(&g_cnt[d.x], 1);
    atomicAdd(&g_cnt[d.y], 1);
    atomicAdd(&g_cnt[d.z], 1);
    atomicAdd(&g_cnt[d.w], 1);
}

// ---------------------------------------------------------------------------
// rowstart = exclusive scan of (cnt[i] + 1); rowstart[n] = m.
__global__ void __launch_bounds__(1024) k_scan(int n, int m) {
    __shared__ int sdata[1024];
    int t = threadIdx.x;
    int chunk = (n + 1023) >> 10;
    int lo = t * chunk;
    int hi = lo + chunk; if (hi > n) hi = n;

    int s = 0;
    for (int i = lo; i < hi; i++) s += g_cnt[i] + 1;
    sdata[t] = s;
    __syncthreads();
#pragma unroll
    for (int off = 1; off < 1024; off <<= 1) {
        int v = (t >= off) ? sdata[t - off] : 0;
        __syncthreads();
        sdata[t] += v;
        __syncthreads();
    }
    int running = sdata[t] - s;
    for (int i = lo; i < hi; i++) {
        g_rowstart[i] = running;
        running += g_cnt[i] + 1;
    }
    if (t == 0) g_rowstart[n] = m;
}

// ---------------------------------------------------------------------------
// h = x @ W (h only).  64x64 tile per block, packed f32x2 FMAs.
__global__ void __launch_bounds__(256) k_gemm(const float* __restrict__ x,
                                              const float* __restrict__ W,
                                              int n) {
    __shared__ float4 Ws4[64 * 16];
    __shared__ float4 Xs4[64 * 16];

    int t = threadIdx.x;
    int fg = t & 15;
    int ng = t >> 4;
    int node0 = blockIdx.x * 64;

    const float4* x4 = (const float4*)x;   // row stride 32 float4
    const float4* W4 = (const float4*)W;   // row stride 16 float4

    unsigned long long acc0[4], acc1[4];
#pragma unroll
    for (int j = 0; j < 4; j++) { acc0[j] = 0ull; acc1[j] = 0ull; }

#pragma unroll
    for (int ck = 0; ck < 2; ck++) {
        if (ck) __syncthreads();
        for (int l = t; l < 1024; l += 256) {
            int r = l >> 4, c = l & 15;
            Ws4[l] = W4[(ck * 64 + r) * 16 + c];
            int node = node0 + r;
            Xs4[l] = (node < n) ? x4[node * 32 + ck * 16 + c]
                                : make_float4(0.f, 0.f, 0.f, 0.f);
        }
        __syncthreads();

#pragma unroll
        for (int kq = 0; kq < 16; kq++) {
            unsigned long long w01[4], w23[4];
#pragma unroll
            for (int kk = 0; kk < 4; kk++) {
                float4 wv = Ws4[(4 * kq + kk) * 16 + fg];
                w01[kk] = pack2(wv.x, wv.y);
                w23[kk] = pack2(wv.z, wv.w);
            }
#pragma unroll
            for (int j = 0; j < 4; j++) {
                float4 xv = Xs4[(ng + 16 * j) * 16 + kq];
                unsigned long long xx;
                xx = pack2(xv.x, xv.x);
                acc0[j] = fma2(xx, w01[0], acc0[j]);
                acc1[j] = fma2(xx, w23[0], acc1[j]);
                xx = pack2(xv.y, xv.y);
                acc0[j] = fma2(xx, w01[1], acc0[j]);
                acc1[j] = fma2(xx, w23[1], acc1[j]);
                xx = pack2(xv.z, xv.z);
                acc0[j] = fma2(xx, w01[2], acc0[j]);
                acc1[j] = fma2(xx, w23[2], acc1[j]);
                xx = pack2(xv.w, xv.w);
                acc0[j] = fma2(xx, w01[3], acc0[j]);
                acc1[j] = fma2(xx, w23[3], acc1[j]);
            }
        }
    }

    float4* h4 = (float4*)g_h;  // row stride 16 float4
#pragma unroll
    for (int j = 0; j < 4; j++) {
        int node = node0 + ng + 16 * j;
        if (node < n) {
            float a, b, c, d;
            unpack2(acc0[j], a, b);
            unpack2(acc1[j], c, d);
            h4[node * 16 + fg] = make_float4(a, b, c, d);
        }
    }
}

// ---------------------------------------------------------------------------
// Fill (R13-exact): csr[rowstart[d]+atomicSub(cnt[d])-1] = {src, exp(lrelu)}.
__global__ void k_fill(const int* __restrict__ ei, int e, int n) {
    int i = blockIdx.x * blockDim.x + threadIdx.x;
    int m = e + n;
    if (i >= m) return;
    int s, d, pos;
    if (i < e) {
        s = ei[i];
        d = ei[e + i];
        pos = g_rowstart[d] + atomicSub(&g_cnt[d], 1) - 1;  // restores cnt->0
    } else {
        s = d = i - e;                 // self loop: fixed last slot of row
        pos = g_rowstart[d + 1] - 1;
    }
    float ee = g_asrc[s] + g_adst[d];
    ee = (ee > 0.0f) ? ee : 0.2f * ee;  // LeakyReLU(0.2)
    g_csr[pos] = make_float2(__int_as_float(s), __expf(ee));
}

// ---------------------------------------------------------------------------
// k_node (R13-exact): shuffle-free, warp-uniform csr broadcast loads.
__global__ void __launch_bounds__(256) k_node(float* __restrict__ out,
                                              const float* __restrict__ bias,
                                              int n) {
    int warp = (blockIdx.x * blockDim.x + threadIdx.x) >> 5;
    int lane = threadIdx.x & 31;
    if (warp >= n) return;

    int row = g_rowstart[warp];
    int end = g_rowstart[warp + 1];

    float acc0 = 0.0f, acc1 = 0.0f, wsum = 0.0f;
    const float2* h2 = (const float2*)g_h;  // row stride 32 float2

#pragma unroll 4
    for (int k = row; k < end; k++) {
        float2 c = __ldg(&g_csr[k]);         // warp-uniform broadcast load
        int   s = __float_as_int(c.x);
        float w = c.y;
        float2 hv = __ldg(&h2[s * 32 + lane]);
        wsum += w;
        acc0 = fmaf(w, hv.x, acc0);
        acc1 = fmaf(w, hv.y, acc1);
    }
    float inv = 1.0f / wsum;

    float2 b = ((const float2*)bias)[lane];
    float o0 = acc0 * inv + b.x;
    float o1 = acc1 * inv + b.y;
    ((float2*)out)[warp * 32 + lane] =
        make_float2(o0 > 0.0f ? o0 : 0.0f, o1 > 0.0f ? o1 : 0.0f);
}

// ---------------------------------------------------------------------------
extern "C" void kernel_launch(void* const* d_in, const int* in_sizes, int n_in,
                              void* d_out, int out_size) {
    const float* x       = (const float*)d_in[0];
    const int*   ei      = (const int*)d_in[1];
    const float* W       = (const float*)d_in[2];
    const float* att_src = (const float*)d_in[3];
    const float* att_dst = (const float*)d_in[4];
    const float* bias    = (const float*)d_in[5];
    float*       out     = (float*)d_out;

    int n = in_sizes[0] / F_IN;   // 50000
    int e = in_sizes[1] / 2;      // 1600000
    int m = e + n;

    // one-time resources (created on the first, non-captured call)
    static cudaStream_t sB = nullptr;
    static cudaEvent_t  evFork = nullptr, evAtt = nullptr, evJoin = nullptr;
    if (!sB) {
        cudaStreamCreateWithFlags(&sB, cudaStreamNonBlocking);
        cudaEventCreateWithFlags(&evFork, cudaEventDisableTiming);
        cudaEventCreateWithFlags(&evAtt,  cudaEventDisableTiming);
        cudaEventCreateWithFlags(&evJoin, cudaEventDisableTiming);
    }

    // fork
    cudaEventRecord(evFork, 0);
    cudaStreamWaitEvent(sB, evFork, 0);

    // stream B: attention scalars first (small), then the GEMM
    k_watt<<<1, 128, 0, sB>>>(W, att_src, att_dst);
    k_att2<<<(n * 32 + 255) / 256, 256, 0, sB>>>(x, n);
    cudaEventRecord(evAtt, sB);
    k_gemm<<<(n + 63) / 64, 256, 0, sB>>>(x, W, n);
    cudaEventRecord(evJoin, sB);

    // stream A (default): CSR construction
    k_build<<<(e / 4 + 255) / 256, 256>>>(ei + e, e / 4);
    k_scan <<<1, 1024>>>(n, m);

    // fill waits only on att2 (+ scan by program order), NOT the GEMM
    cudaStreamWaitEvent(0, evAtt, 0);
    k_fill<<<(m + 255) / 256, 256>>>(ei, e, n);

    // node needs h
    cudaStreamWaitEvent(0, evJoin, 0);
    k_node<<<(n * 32 + 255) / 256, 256>>>(out, bias, n);
}

// round 17
// speedup vs baseline: 1.1639x; 1.1639x over previous
#include <cuda_runtime.h>

// GATConv forward (heads=1): N=50000, E=1600000, F_IN=128, F_OUT=64.
// edge_index is INT32. CSR-by-destination, no float atomics, no max-pass
// (softmax is shift-invariant; e is bounded so exp() is safe in fp32).
//
// FINAL configuration (R13, best measured 148.3us over 16 rounds):
//   stream A: k_build (pure REDG histogram) -> k_scan (rowstart)
//   stream B: k_gemm  (h = x@W, 64x64 tile, fma.rn.f32x2; fused att dots)
//   join:     k_fill  (pos = rowstart[d] + atomicSub(cnt[d]) - 1)
//             k_node  (shuffle-free: warp-uniform csr broadcast loads)

#define F_IN  128
#define F_OUT 64
#define MAXN  50000
#define MAXE  1600000
#define MAXM  (MAXE + MAXN)

__device__ __align__(16) float g_h[(size_t)MAXN * F_OUT];
__device__ float  g_asrc[MAXN];
__device__ float  g_adst[MAXN];
__device__ int    g_cnt[MAXN];          // zero-init (BSS); k_fill restores to 0
__device__ int    g_rowstart[MAXN + 1];
__device__ __align__(8) float2 g_csr[MAXM];  // .x = src bits, .y = exp(e)

// ---- packed f32x2 helpers (sm_103a) ---------------------------------------
__device__ __forceinline__ unsigned long long pack2(float a, float b) {
    unsigned long long r;
    asm("mov.b64 %0, {%1, %2};" : "=l"(r) : "f"(a), "f"(b));
    return r;
}
__device__ __forceinline__ void unpack2(unsigned long long v, float& a, float& b) {
    asm("mov.b64 {%0, %1}, %2;" : "=f"(a), "=f"(b) : "l"(v));
}
__device__ __forceinline__ unsigned long long fma2(unsigned long long a,
                                                   unsigned long long b,
                                                   unsigned long long c) {
    unsigned long long d;
    asm("fma.rn.f32x2 %0, %1, %2, %3;" : "=l"(d) : "l"(a), "l"(b), "l"(c));
    return d;
}

// ---------------------------------------------------------------------------
// Pure histogram: atomicAdd return unused -> compiles to REDG (no round trip).
__global__ void k_build(const int* __restrict__ dst4, int e4) {
    int i = blockIdx.x * blockDim.x + threadIdx.x;
    if (i >= e4) return;
    int4 d = ((const int4*)dst4)[i];
    atomicAdd(&g_cnt[d.x], 1);
    atomicAdd(&g_cnt[d.y], 1);
    atomicAdd(&g_cnt[d.z], 1);
    atomicAdd(&g_cnt[d.w], 1);
}

// ---------------------------------------------------------------------------
// rowstart = exclusive scan of (cnt[i] + 1); rowstart[n] = m.
__global__ void __launch_bounds__(1024) k_scan(int n, int m) {
    __shared__ int sdata[1024];
    int t = threadIdx.x;
    int chunk = (n + 1023) >> 10;
    int lo = t * chunk;
    int hi = lo + chunk; if (hi > n) hi = n;

    int s = 0;
    for (int i = lo; i < hi; i++) s += g_cnt[i] + 1;
    sdata[t] = s;
    __syncthreads();
#pragma unroll
    for (int off = 1; off < 1024; off <<= 1) {
        int v = (t >= off) ? sdata[t - off] : 0;
        __syncthreads();
        sdata[t] += v;
        __syncthreads();
    }
    int running = sdata[t] - s;
    for (int i = lo; i < hi; i++) {
        g_rowstart[i] = running;
        running += g_cnt[i] + 1;
    }
    if (t == 0) g_rowstart[n] = m;
}

// ---------------------------------------------------------------------------
// h = x @ W with fused attention dots.  64 nodes x 64 features per block,
// 256 threads; thread (fg = t&15, ng = t>>4) owns nodes {ng+16j} x features
// [4fg,4fg+4).  Epilogue: 16-lane shuffle reduction -> a_src/a_dst per node.
__global__ void __launch_bounds__(256) k_gemm(const float* __restrict__ x,
                                              const float* __restrict__ W,
                                              const float* __restrict__ att_src,
                                              const float* __restrict__ att_dst,
                                              int n) {
    __shared__ float4 Ws4[64 * 16];  // [k within chunk][feature-quad]   16 KB
    __shared__ float4 Xs4[64 * 16];  // [node within tile][k-quad]       16 KB

    int t = threadIdx.x;
    int fg = t & 15;
    int ng = t >> 4;
    int node0 = blockIdx.x * 64;

    const float4* x4 = (const float4*)x;   // row stride 32 float4
    const float4* W4 = (const float4*)W;   // row stride 16 float4

    unsigned long long acc0[4], acc1[4];
#pragma unroll
    for (int j = 0; j < 4; j++) { acc0[j] = 0ull; acc1[j] = 0ull; }

#pragma unroll
    for (int ck = 0; ck < 2; ck++) {
        if (ck) __syncthreads();
        for (int l = t; l < 1024; l += 256) {
            int r = l >> 4, c = l & 15;
            Ws4[l] = W4[(ck * 64 + r) * 16 + c];
            int node = node0 + r;
            Xs4[l] = (node < n) ? x4[node * 32 + ck * 16 + c]
                                : make_float4(0.f, 0.f, 0.f, 0.f);
        }
        __syncthreads();

#pragma unroll
        for (int kq = 0; kq < 16; kq++) {
            unsigned long long w01[4], w23[4];
#pragma unroll
            for (int kk = 0; kk < 4; kk++) {
                float4 wv = Ws4[(4 * kq + kk) * 16 + fg];
                w01[kk] = pack2(wv.x, wv.y);
                w23[kk] = pack2(wv.z, wv.w);
            }
#pragma unroll
            for (int j = 0; j < 4; j++) {
                float4 xv = Xs4[(ng + 16 * j) * 16 + kq];
                unsigned long long xx;
                xx = pack2(xv.x, xv.x);
                acc0[j] = fma2(xx, w01[0], acc0[j]);
                acc1[j] = fma2(xx, w23[0], acc1[j]);
                xx = pack2(xv.y, xv.y);
                acc0[j] = fma2(xx, w01[1], acc0[j]);
                acc1[j] = fma2(xx, w23[1], acc1[j]);
                xx = pack2(xv.z, xv.z);
                acc0[j] = fma2(xx, w01[2], acc0[j]);
                acc1[j] = fma2(xx, w23[2], acc1[j]);
                xx = pack2(xv.w, xv.w);
                acc0[j] = fma2(xx, w01[3], acc0[j]);
                acc1[j] = fma2(xx, w23[3], acc1[j]);
            }
        }
    }

    float4 as = ((const float4*)att_src)[fg];
    float4 ad = ((const float4*)att_dst)[fg];
    float4* h4 = (float4*)g_h;  // row stride 16 float4

#pragma unroll
    for (int j = 0; j < 4; j++) {
        int node = node0 + ng + 16 * j;
        float a, b, c, d;
        unpack2(acc0[j], a, b);
        unpack2(acc1[j], c, d);
        // partial attention dots over this thread's 4 features
        float ps = a * as.x + b * as.y + c * as.z + d * as.w;
        float pd = a * ad.x + b * ad.y + c * ad.z + d * ad.w;
#pragma unroll
        for (int o = 8; o > 0; o >>= 1) {   // reduce across the 16-lane group
            ps += __shfl_xor_sync(0xFFFFFFFFu, ps, o);
            pd += __shfl_xor_sync(0xFFFFFFFFu, pd, o);
        }
        if (node < n) {
            h4[node * 16 + fg] = make_float4(a, b, c, d);
            if (fg == 0) {
                g_asrc[node] = ps;
                g_adst[node] = pd;
            }
        }
    }
}

// ---------------------------------------------------------------------------
__global__ void k_fill(const int* __restrict__ ei, int e, int n) {
    int i = blockIdx.x * blockDim.x + threadIdx.x;
    int m = e + n;
    if (i >= m) return;
    int s, d, pos;
    if (i < e) {
        s = ei[i];
        d = ei[e + i];
        pos = g_rowstart[d] + atomicSub(&g_cnt[d], 1) - 1;  // restores cnt->0
    } else {
        s = d = i - e;                 // self loop: fixed last slot of row
        pos = g_rowstart[d + 1] - 1;
    }
    float ee = g_asrc[s] + g_adst[d];
    ee = (ee > 0.0f) ? ee : 0.2f * ee;  // LeakyReLU(0.2)
    g_csr[pos] = make_float2(__int_as_float(s), __expf(ee));
}

// ---------------------------------------------------------------------------
// One warp per destination, SHUFFLE-FREE: every lane issues the SAME csr[k]
// load (L1 broadcast, one 8B sector, 16 edges per 128B line) so {s, w} are
// warp-uniform registers.  Per edge: uniform LDG.64 + gathered LDG.64 + 2 FMA.
// wsum is uniform in every lane -> no reduction needed.
__global__ void __launch_bounds__(256) k_node(float* __restrict__ out,
                                              const float* __restrict__ bias,
                                              int n) {
    int warp = (blockIdx.x * blockDim.x + threadIdx.x) >> 5;
    int lane = threadIdx.x & 31;
    if (warp >= n) return;

    int row = g_rowstart[warp];
    int end = g_rowstart[warp + 1];

    float acc0 = 0.0f, acc1 = 0.0f, wsum = 0.0f;
    const float2* h2 = (const float2*)g_h;  // row stride 32 float2

#pragma unroll 4
    for (int k = row; k < end; k++) {
        float2 c = __ldg(&g_csr[k]);         // warp-uniform broadcast load
        int   s = __float_as_int(c.x);
        float w = c.y;
        float2 hv = __ldg(&h2[s * 32 + lane]);
        wsum += w;
        acc0 = fmaf(w, hv.x, acc0);
        acc1 = fmaf(w, hv.y, acc1);
    }
    float inv = 1.0f / wsum;

    float2 b = ((const float2*)bias)[lane];
    float o0 = acc0 * inv + b.x;
    float o1 = acc1 * inv + b.y;
    ((float2*)out)[warp * 32 + lane] =
        make_float2(o0 > 0.0f ? o0 : 0.0f, o1 > 0.0f ? o1 : 0.0f);
}

// ---------------------------------------------------------------------------
extern "C" void kernel_launch(void* const* d_in, const int* in_sizes, int n_in,
                              void* d_out, int out_size) {
    const float* x       = (const float*)d_in[0];
    const int*   ei      = (const int*)d_in[1];
    const float* W       = (const float*)d_in[2];
    const float* att_src = (const float*)d_in[3];
    const float* att_dst = (const float*)d_in[4];
    const float* bias    = (const float*)d_in[5];
    float*       out     = (float*)d_out;

    int n = in_sizes[0] / F_IN;   // 50000
    int e = in_sizes[1] / 2;      // 1600000
    int m = e + n;

    // one-time resources (created on the first, non-captured call)
    static cudaStream_t sB = nullptr;
    static cudaEvent_t  evFork = nullptr, evJoin = nullptr;
    if (!sB) {
        cudaStreamCreateWithFlags(&sB, cudaStreamNonBlocking);
        cudaEventCreateWithFlags(&evFork, cudaEventDisableTiming);
        cudaEventCreateWithFlags(&evJoin, cudaEventDisableTiming);
    }

    // fork: GEMM(+att) on sB, histogram+scan on the main stream
    cudaEventRecord(evFork, 0);
    cudaStreamWaitEvent(sB, evFork, 0);

    k_gemm<<<(n + 63) / 64, 256, 0, sB>>>(x, W, att_src, att_dst, n);
    cudaEventRecord(evJoin, sB);

    k_build<<<(e / 4 + 255) / 256, 256>>>(ei + e, e / 4);
    k_scan <<<1, 1024>>>(n, m);

    // join: fill needs scan + gemm(att) results
    cudaStreamWaitEvent(0, evJoin, 0);

    k_fill<<<(m + 255) / 256, 256>>>(ei, e, n);
    k_node<<<(n * 32 + 255) / 256, 256>>>(out, bias, n);
}